// round 2
// baseline (speedup 1.0000x reference)
#include <cuda_runtime.h>

// Problem dims
#define BB   16
#define HH   256
#define WW   256
#define CC   32
#define EM0_ 16
#define EM1_ 17
#define NKH  32   // 2*EM0 retained row-frequencies

// Scratch + tables (static __device__ arrays: allocation-free)
__device__ float2 g_twW[EM1_ * WW];          // (cos,sin) of 2*pi*kw*w/256
__device__ float2 g_twH[NKH * HH];           // (cos,sin) of 2*pi*m*h/256, m signed
__device__ float2 g_Xw[BB * HH * EM1_ * CC]; // after W-DFT
__device__ float2 g_Xm[BB * NKH * EM1_ * CC];// after H-DFT (modes, input chans)
__device__ float2 g_Md[BB * NKH * EM1_ * CC];// after mixing (output chans, x2 fold)
__device__ float2 g_Z [BB * HH * EM1_ * CC]; // after inverse H-DFT
__device__ float2 g_wT[NKH * EM1_ * CC * CC];// weights transposed [kh][kw][i][o]

// ---------------------------------------------------------------------------
// Twiddle tables. p = (k*w) mod 256 via & (two's complement handles negatives).
__global__ void k_init_tw() {
    int idx = blockIdx.x * blockDim.x + threadIdx.x;
    if (idx < EM1_ * WW) {
        int k = idx / WW, w = idx % WW;
        int p = (k * w) & 255;
        float s, c;
        sincospif((float)p / 128.0f, &s, &c);
        g_twW[idx] = make_float2(c, s);
    } else if (idx < EM1_ * WW + NKH * HH) {
        int j = idx - EM1_ * WW;
        int kidx = j / HH, h = j % HH;
        int m = (kidx < EM0_) ? kidx : kidx - NKH;   // rows 240..255 -> -16..-1
        int p = (m * h) & 255;
        float s, c;
        sincospif((float)p / 128.0f, &s, &c);
        g_twH[j] = make_float2(c, s);
    }
}

// ---------------------------------------------------------------------------
// Weight transpose: w{1,2}_{r,i}[i][o][khm][kw] -> g_wT[kh][kw][i][o] (float2)
__global__ void k_wt(const float* __restrict__ w1r, const float* __restrict__ w1i,
                     const float* __restrict__ w2r, const float* __restrict__ w2i) {
    int idx = blockIdx.x * blockDim.x + threadIdx.x;
    if (idx >= NKH * EM1_ * CC * CC) return;
    int o = idx & 31;
    int t = idx >> 5;
    int i = t & 31; t >>= 5;
    int kw = t % EM1_;
    int kh = t / EM1_;
    int khm = (kh < EM0_) ? kh : kh - EM0_;
    const float* wr = (kh < EM0_) ? w1r : w2r;
    const float* wi = (kh < EM0_) ? w1i : w2i;
    int s = ((i * CC + o) * EM0_ + khm) * EM1_ + kw;
    g_wT[idx] = make_float2(wr[s], wi[s]);
}

// ---------------------------------------------------------------------------
// Stage A: partial real DFT along W (17 bins), 4 h-rows per block.
// Xw[b,h,kw,i] = (1/65536) * sum_w x[b,h,w,i] * e^{-2pi i kw w/256}
__global__ void __launch_bounds__(544) kA(const float* __restrict__ x) {
    extern __shared__ float xs[];   // [w][i][hh]  256*32*4 floats = 128KB
    int blk = blockIdx.x;
    int b  = blk >> 6;
    int h0 = (blk & 63) << 2;
    const float* xb = x + ((size_t)b * HH + h0) * (WW * CC);
    int tid = threadIdx.x;
    for (int idx = tid; idx < 4 * WW * CC; idx += 544) {
        int hh  = idx >> 13;          // 8192 = WW*CC
        int rem = idx & 8191;         // w*32 + i
        xs[rem * 4 + hh] = xb[hh * (WW * CC) + rem];
    }
    __syncthreads();
    int kw = tid >> 5, i = tid & 31;  // warp-uniform kw
    float sr0 = 0, sr1 = 0, sr2 = 0, sr3 = 0;
    float si0 = 0, si1 = 0, si2 = 0, si3 = 0;
    const float2* tw = g_twW + kw * WW;
#pragma unroll 4
    for (int w = 0; w < WW; w++) {
        float2 cs = __ldg(&tw[w]);                       // broadcast, L1-hot
        float4 xv = *(const float4*)&xs[(w * CC + i) * 4];
        sr0 = fmaf(xv.x, cs.x, sr0);  si0 = fmaf(xv.x, cs.y, si0);
        sr1 = fmaf(xv.y, cs.x, sr1);  si1 = fmaf(xv.y, cs.y, si1);
        sr2 = fmaf(xv.z, cs.x, sr2);  si2 = fmaf(xv.z, cs.y, si2);
        sr3 = fmaf(xv.w, cs.x, sr3);  si3 = fmaf(xv.w, cs.y, si3);
    }
    const float sc = 1.0f / 65536.0f; // forward norm 1/(H*W)
    size_t base = ((size_t)(b * HH + h0) * EM1_ + kw) * CC + i;
    g_Xw[base               ] = make_float2(sr0 * sc, -si0 * sc);
    g_Xw[base +     EM1_*CC ] = make_float2(sr1 * sc, -si1 * sc);
    g_Xw[base + 2 * EM1_*CC ] = make_float2(sr2 * sc, -si2 * sc);
    g_Xw[base + 3 * EM1_*CC ] = make_float2(sr3 * sc, -si3 * sc);
}

// ---------------------------------------------------------------------------
// Stage B: complex DFT along H onto 32 signed row-frequencies.
// Xm[b,kh,kw,i] = sum_h Xw[b,h,kw,i] * e^{-i th},  (c,s)=table -> (c - i s)
__global__ void __launch_bounds__(1024) kB() {
    extern __shared__ float2 xsc[];   // [h][i] 256*32 float2 = 64KB
    int b  = blockIdx.x / EM1_;
    int kw = blockIdx.x % EM1_;
    int tid = threadIdx.x;
    for (int idx = tid; idx < HH * CC; idx += 1024) {
        int h = idx >> 5, i = idx & 31;
        xsc[idx] = g_Xw[((size_t)(b * HH + h) * EM1_ + kw) * CC + i];
    }
    __syncthreads();
    int kh = tid >> 5, i = tid & 31;
    float orr = 0, oii = 0;
    const float2* tw = g_twH + kh * HH;
#pragma unroll 4
    for (int h = 0; h < HH; h++) {
        float2 v  = xsc[h * CC + i];
        float2 cs = __ldg(&tw[h]);
        orr = fmaf(v.x, cs.x, orr); orr = fmaf(v.y, cs.y, orr);
        oii = fmaf(v.y, cs.x, oii); oii = fmaf(-v.x, cs.y, oii);
    }
    g_Xm[((b * NKH + kh) * EM1_ + kw) * CC + i] = make_float2(orr, oii);
}

// ---------------------------------------------------------------------------
// Stage C: complex channel mixing + Hermitian x2 fold (kw>0).
__global__ void __launch_bounds__(544) kC() {
    __shared__ float2 xm[EM1_ * CC];
    int b  = blockIdx.x >> 5;
    int kh = blockIdx.x & 31;
    int tid = threadIdx.x;
    xm[tid] = g_Xm[(b * NKH + kh) * (EM1_ * CC) + tid]; // 544 == EM1_*CC
    __syncthreads();
    int kw = tid >> 5, o = tid & 31;
    float orr = 0, oii = 0;
    const float2* wp = g_wT + (kh * EM1_ + kw) * (CC * CC);
    const float2* xp = xm + kw * CC;
#pragma unroll
    for (int i = 0; i < CC; i++) {
        float2 xv = xp[i];                  // broadcast in warp
        float2 wv = __ldg(&wp[i * CC + o]); // coalesced, L2-resident
        orr = fmaf(xv.x, wv.x, orr); orr = fmaf(-xv.y, wv.y, orr);
        oii = fmaf(xv.x, wv.y, oii); oii = fmaf( xv.y, wv.x, oii);
    }
    float f = (kw == 0) ? 1.0f : 2.0f;
    g_Md[(b * NKH + kh) * (EM1_ * CC) + tid] = make_float2(orr * f, oii * f);
}

// ---------------------------------------------------------------------------
// Stage D1: inverse DFT along H (e^{+i th}), 8 h-rows per block.
__global__ void __launch_bounds__(544) kD1() {
    extern __shared__ float2 md[];   // [kh][kw*32+o] 32*544 float2 = 136KB
    int b  = blockIdx.x >> 5;
    int h0 = (blockIdx.x & 31) << 3;
    int tid = threadIdx.x;
    for (int idx = tid; idx < NKH * 544; idx += 544)
        md[idx] = g_Md[b * (NKH * 544) + idx];
    __syncthreads();
    float zr[8] = {0,0,0,0,0,0,0,0};
    float zi[8] = {0,0,0,0,0,0,0,0};
#pragma unroll 2
    for (int kh = 0; kh < NKH; kh++) {
        float2 m = md[kh * 544 + tid];
        const float2* tw = g_twH + kh * HH + h0;
#pragma unroll
        for (int hh = 0; hh < 8; hh++) {
            float2 cs = __ldg(&tw[hh]);
            zr[hh] = fmaf(m.x, cs.x, zr[hh]); zr[hh] = fmaf(-m.y, cs.y, zr[hh]);
            zi[hh] = fmaf(m.x, cs.y, zi[hh]); zi[hh] = fmaf( m.y, cs.x, zi[hh]);
        }
    }
#pragma unroll
    for (int hh = 0; hh < 8; hh++)
        g_Z[(size_t)(b * HH + h0 + hh) * (EM1_ * CC) + tid] =
            make_float2(zr[hh], zi[hh]);
}

// ---------------------------------------------------------------------------
// Stage D2: inverse real DFT along W + bias.
// y[b,h,w,o] = bias[o] + sum_kw ( Zr*cos - Zi*sin )   (x2 fold already applied)
__global__ void __launch_bounds__(256) kD2(const float* __restrict__ bias,
                                           float* __restrict__ y) {
    __shared__ float2 zs[EM1_ * CC];
    __shared__ float  bs[CC];
    int b = blockIdx.x >> 8;
    int h = blockIdx.x & 255;
    int tid = threadIdx.x;
    for (int idx = tid; idx < EM1_ * CC; idx += 256)
        zs[idx] = g_Z[(size_t)(b * HH + h) * (EM1_ * CC) + idx];
    if (tid < CC) bs[tid] = bias[tid];
    __syncthreads();
    int o = tid & 31, wslot = tid >> 5;   // warp-uniform w
    float zr[EM1_], zi[EM1_];
#pragma unroll
    for (int kw = 0; kw < EM1_; kw++) {
        float2 v = zs[kw * CC + o];
        zr[kw] = v.x; zi[kw] = v.y;
    }
    float bo = bs[o];
    float* yp = y + ((size_t)(b * HH + h) * WW) * CC;
    for (int wi = 0; wi < 32; wi++) {
        int w = wslot * 32 + wi;
        float acc = bo;
#pragma unroll
        for (int kw = 0; kw < EM1_; kw++) {
            float2 cs = __ldg(&g_twW[kw * WW + w]);  // uniform addr, L1-hot
            acc = fmaf(zr[kw], cs.x, acc);
            acc = fmaf(-zi[kw], cs.y, acc);
        }
        yp[w * CC + o] = acc;
    }
}

// ---------------------------------------------------------------------------
extern "C" void kernel_launch(void* const* d_in, const int* in_sizes, int n_in,
                              void* d_out, int out_size) {
    const float* x    = (const float*)d_in[0];
    const float* w1r  = (const float*)d_in[1];
    const float* w1i  = (const float*)d_in[2];
    const float* w2r  = (const float*)d_in[3];
    const float* w2i  = (const float*)d_in[4];
    const float* bias = (const float*)d_in[5];
    float* y = (float*)d_out;

    cudaFuncSetAttribute(kA,  cudaFuncAttributeMaxDynamicSharedMemorySize,
                         4 * WW * CC * (int)sizeof(float));        // 128KB
    cudaFuncSetAttribute(kB,  cudaFuncAttributeMaxDynamicSharedMemorySize,
                         HH * CC * (int)sizeof(float2));           // 64KB
    cudaFuncSetAttribute(kD1, cudaFuncAttributeMaxDynamicSharedMemorySize,
                         NKH * 544 * (int)sizeof(float2));         // 136KB

    k_init_tw<<<(EM1_ * WW + NKH * HH + 255) / 256, 256>>>();
    k_wt<<<(NKH * EM1_ * CC * CC + 255) / 256, 256>>>(w1r, w1i, w2r, w2i);
    kA <<<BB * HH / 4, 544, 4 * WW * CC * (int)sizeof(float)>>>(x);
    kB <<<BB * EM1_, 1024, HH * CC * (int)sizeof(float2)>>>();
    kC <<<BB * NKH, 544>>>();
    kD1<<<BB * HH / 8, 544, NKH * 544 * (int)sizeof(float2)>>>();
    kD2<<<BB * HH, 256>>>(bias, y);
}

// round 4
// speedup vs baseline: 1.2741x; 1.2741x over previous
#include <cuda_runtime.h>

// Problem dims
#define BB   16
#define HH   256
#define WW   256
#define CC   32
#define EM0_ 16
#define EM1_ 17
#define NKH  32

typedef unsigned long long u64;

// ---- packed f32x2 helpers (FFMA2 only reachable via PTX) ----
__device__ __forceinline__ u64 ffma2(u64 a, u64 b, u64 c) {
    u64 d;
    asm("fma.rn.f32x2 %0, %1, %2, %3;" : "=l"(d) : "l"(a), "l"(b), "l"(c));
    return d;
}
__device__ __forceinline__ float2 upk(u64 v) {
    float2 r;
    asm("mov.b64 {%0,%1}, %2;" : "=f"(r.x), "=f"(r.y) : "l"(v));
    return r;
}
__device__ __forceinline__ u64 pk(float x, float y) {
    u64 v;
    asm("mov.b64 %0, {%1,%2};" : "=l"(v) : "f"(x), "f"(y));
    return v;
}

// ---- tables (packed for direct u64 operand loads) ----
__device__ float2 g_tA [128 * EM1_];   // [w'][bin]  (c, -s)
__device__ float4 g_tB [NKH * 128];    // [kh][h']   (c, c, s, -s)
__device__ float4 g_tD1[EM1_ * HH];    // [r][h]     (c, c, -s, s)
__device__ float2 g_tD2[129 * EM1_];   // [w'][kw]   (c, s)

// ---- scratch ----
__device__ float2 g_Xw[BB * HH * EM1_ * CC];
__device__ float2 g_Xm[BB * NKH * EM1_ * CC];
__device__ float2 g_Md[BB * NKH * EM1_ * CC];
__device__ float2 g_Z [BB * HH * EM1_ * CC];
__device__ float2 g_wT[NKH * EM1_ * CC * CC];

// ---------------------------------------------------------------------------
__global__ void k_init() {
    int idx = blockIdx.x * 256 + threadIdx.x;
    if (idx < 128 * EM1_) {                       // tA
        int w = idx / EM1_, k = idx % EM1_;
        int p = (k * w) & 255;
        float s, c; sincospif((float)p / 128.0f, &s, &c);
        g_tA[idx] = make_float2(c, -s);
    }
    int j = idx - 128 * EM1_;
    if (j >= 0 && j < NKH * 128) {                // tB
        int kh = j >> 7, h = j & 127;
        int m = (kh < EM0_) ? kh : kh - NKH;
        int p = (m * h) & 255;
        float s, c; sincospif((float)p / 128.0f, &s, &c);
        g_tB[j] = make_float4(c, c, s, -s);
    }
    int e = j - NKH * 128;
    if (e >= 0 && e < EM1_ * HH) {                // tD1
        int r = e >> 8, h = e & 255;
        int m = (r < 16) ? r : -16;
        int p = (m * h) & 255;
        float s, c; sincospif((float)p / 128.0f, &s, &c);
        g_tD1[e] = make_float4(c, c, -s, s);
    }
    int f = e - EM1_ * HH;
    if (f >= 0 && f < 129 * EM1_) {               // tD2
        int w = f / EM1_, k = f % EM1_;
        int p = (k * w) & 255;
        float s, c; sincospif((float)p / 128.0f, &s, &c);
        g_tD2[f] = make_float2(c, s);
    }
}

// ---------------------------------------------------------------------------
__global__ void k_wt(const float* __restrict__ w1r, const float* __restrict__ w1i,
                     const float* __restrict__ w2r, const float* __restrict__ w2i) {
    int idx = blockIdx.x * blockDim.x + threadIdx.x;
    if (idx >= NKH * EM1_ * CC * CC) return;
    int o = idx & 31;
    int t = idx >> 5;
    int i = t & 31; t >>= 5;
    int kw = t % EM1_;
    int kh = t / EM1_;
    int khm = (kh < EM0_) ? kh : kh - EM0_;
    const float* wr = (kh < EM0_) ? w1r : w2r;
    const float* wi = (kh < EM0_) ? w1i : w2i;
    int s = ((i * CC + o) * EM0_ + khm) * EM1_ + kw;
    g_wT[idx] = make_float2(wr[s], wi[s]);
}

// ---------------------------------------------------------------------------
// Stage A: folded partial real DFT along W. Block = 2 h rows.
// Threads: 80 = 16 ch-pairs x 5 bin-groups ({0-3},{4-7},{8-11},{12-15},{16}).
// smem: sd[h][w'*16 + ipair] float4 = (s_i0, d_i0, s_i1, d_i1)
__global__ void __launch_bounds__(80) kA(const float* __restrict__ x) {
    extern __shared__ float4 sd[];   // 2*2048 float4 = 64KB
    int b  = blockIdx.x >> 7;
    int h0 = (blockIdx.x & 127) << 1;
    const float* xb = x + ((size_t)(b * HH + h0)) * (WW * CC);
    int tid = threadIdx.x;

    for (int p = tid; p < 2048; p += 80) {
        int wp = p >> 4;
        int c4 = p & 15;
        int h  = c4 >> 3;
        int ch = c4 & 7;
        int partner = wp ? (256 - wp) : 128;
        float4 a = *(const float4*)&xb[h * (WW * CC) + wp * CC + ch * 4];
        float4 e = *(const float4*)&xb[h * (WW * CC) + partner * CC + ch * 4];
        int base = h * 2048 + wp * 16 + ch * 2;
        sd[base    ] = make_float4(a.x + e.x, a.x - e.x, a.y + e.y, a.y - e.y);
        sd[base + 1] = make_float4(a.z + e.z, a.z - e.z, a.w + e.w, a.w - e.w);
    }
    __syncthreads();

    int islot = tid & 15, grp = tid >> 4;
    int bin0 = grp * 4;
    int nb = (grp == 4) ? 1 : 4;

    u64 acc[4][2][2];
    {   // w'=0 boundary: re0 = (bin even) ? (x0+x128) : (x0-x128)
        float4 z0 = sd[islot];
        float4 z1 = sd[2048 + islot];
#pragma unroll
        for (int bb = 0; bb < 4; bb++) {
            bool odd = (bin0 + bb) & 1;
            acc[bb][0][0] = pk(odd ? z0.y : z0.x, 0.0f);
            acc[bb][0][1] = pk(odd ? z0.w : z0.z, 0.0f);
            acc[bb][1][0] = pk(odd ? z1.y : z1.x, 0.0f);
            acc[bb][1][1] = pk(odd ? z1.w : z1.z, 0.0f);
        }
    }
    const u64* tA = (const u64*)g_tA;
#pragma unroll 2
    for (int wp = 1; wp < 128; wp++) {
        ulonglong2 qa = *(const ulonglong2*)&sd[wp * 16 + islot];
        ulonglong2 qb = *(const ulonglong2*)&sd[2048 + wp * 16 + islot];
#pragma unroll
        for (int bb = 0; bb < 4; bb++) {
            if (bb < nb) {
                u64 t = __ldg(&tA[wp * EM1_ + bin0 + bb]);
                acc[bb][0][0] = ffma2(qa.x, t, acc[bb][0][0]);
                acc[bb][0][1] = ffma2(qa.y, t, acc[bb][0][1]);
                acc[bb][1][0] = ffma2(qb.x, t, acc[bb][1][0]);
                acc[bb][1][1] = ffma2(qb.y, t, acc[bb][1][1]);
            }
        }
    }
    const float sc = 1.0f / 65536.0f;   // forward norm 1/(H*W)
#pragma unroll
    for (int bb = 0; bb < 4; bb++) {
        if (bb < nb) {
#pragma unroll
            for (int h = 0; h < 2; h++)
#pragma unroll
                for (int ii = 0; ii < 2; ii++) {
                    float2 v = upk(acc[bb][h][ii]);
                    g_Xw[((size_t)(b * HH + h0 + h) * EM1_ + bin0 + bb) * CC
                         + islot * 2 + ii] = make_float2(v.x * sc, v.y * sc);
                }
        }
    }
}

// ---------------------------------------------------------------------------
// Stage B: folded complex DFT along H. Block = (b, kw). 256 thr = 32 i x 8 grp(4 kh).
__global__ void __launch_bounds__(256) kB() {
    extern __shared__ float4 sdB[];  // 127*32 float4 (S.x,S.y,D.y,D.x)
    int b  = blockIdx.x / EM1_;
    int kw = blockIdx.x % EM1_;
    int tid = threadIdx.x;
    for (int idx = tid; idx < 127 * 32; idx += 256) {
        int hp = (idx >> 5) + 1, i = idx & 31;
        float2 v  = g_Xw[((size_t)(b * HH + hp) * EM1_ + kw) * CC + i];
        float2 vp = g_Xw[((size_t)(b * HH + 256 - hp) * EM1_ + kw) * CC + i];
        sdB[idx] = make_float4(v.x + vp.x, v.y + vp.y, v.y - vp.y, v.x - vp.x);
    }
    __syncthreads();
    int i = tid & 31, grp = tid >> 5;
    float2 v0  = g_Xw[((size_t)(b * HH) * EM1_ + kw) * CC + i];
    float2 v12 = g_Xw[((size_t)(b * HH + 128) * EM1_ + kw) * CC + i];
    u64 acc[4];
#pragma unroll
    for (int t = 0; t < 4; t++) {
        int kh = grp * 4 + t;
        float p = (kh & 1) ? -1.0f : 1.0f;
        acc[t] = ffma2(pk(v12.x, v12.y), pk(p, p), pk(v0.x, v0.y));
    }
    const ulonglong2* tB = (const ulonglong2*)g_tB;
#pragma unroll 2
    for (int hp = 1; hp < 128; hp++) {
        ulonglong2 q = *(const ulonglong2*)&sdB[(hp - 1) * 32 + i];
#pragma unroll
        for (int t = 0; t < 4; t++) {
            ulonglong2 tb = __ldg(&tB[(grp * 4 + t) * 128 + hp]);
            acc[t] = ffma2(q.x, tb.x, acc[t]);
            acc[t] = ffma2(q.y, tb.y, acc[t]);
        }
    }
#pragma unroll
    for (int t = 0; t < 4; t++) {
        float2 r = upk(acc[t]);
        g_Xm[((size_t)(b * NKH + grp * 4 + t) * EM1_ + kw) * CC + i] =
            make_float2(r.x, r.y);
    }
}

// ---------------------------------------------------------------------------
// Stage C: complex channel mixing + Hermitian x2 fold (unchanged).
__global__ void __launch_bounds__(544) kC() {
    __shared__ float2 xm[EM1_ * CC];
    int b  = blockIdx.x >> 5;
    int kh = blockIdx.x & 31;
    int tid = threadIdx.x;
    xm[tid] = g_Xm[(b * NKH + kh) * (EM1_ * CC) + tid];
    __syncthreads();
    int kw = tid >> 5, o = tid & 31;
    float orr = 0, oii = 0;
    const float2* wp = g_wT + (kh * EM1_ + kw) * (CC * CC);
    const float2* xp = xm + kw * CC;
#pragma unroll
    for (int i = 0; i < CC; i++) {
        float2 xv = xp[i];
        float2 wv = __ldg(&wp[i * CC + o]);
        orr = fmaf(xv.x, wv.x, orr); orr = fmaf(-xv.y, wv.y, orr);
        oii = fmaf(xv.x, wv.y, oii); oii = fmaf( xv.y, wv.x, oii);
    }
    float f = (kw == 0) ? 1.0f : 2.0f;
    g_Md[(b * NKH + kh) * (EM1_ * CC) + tid] = make_float2(orr * f, oii * f);
}

// ---------------------------------------------------------------------------
// Stage D1: folded inverse DFT along H. 17 pair-rows, 8 h per thread.
__global__ void __launch_bounds__(544) kD1() {
    extern __shared__ float4 SD[];   // 17*544 float4 = 148KB
    int b  = blockIdx.x >> 5;
    int h0 = (blockIdx.x & 31) << 3;
    int tid = threadIdx.x;
    const float2* Mb = g_Md + (size_t)b * NKH * 544;
    for (int r = 0; r < 17; r++) {
        float2 S, D;
        if (r == 0)       { float2 m = Mb[tid];            S = m; D = m; }
        else if (r == 16) { float2 m = Mb[16 * 544 + tid]; S = m; D = m; }
        else {
            float2 m1 = Mb[r * 544 + tid];
            float2 m2 = Mb[(32 - r) * 544 + tid];
            S = make_float2(m1.x + m2.x, m1.y + m2.y);
            D = make_float2(m1.x - m2.x, m1.y - m2.y);
        }
        SD[r * 544 + tid] = make_float4(S.x, S.y, D.y, D.x);
    }
    __syncthreads();
    u64 acc[8];
#pragma unroll
    for (int hh = 0; hh < 8; hh++) acc[hh] = 0ull;
    const ulonglong2* tD = (const ulonglong2*)g_tD1;
    for (int r = 0; r < 17; r++) {
        ulonglong2 q = *(const ulonglong2*)&SD[r * 544 + tid];
#pragma unroll
        for (int hh = 0; hh < 8; hh++) {
            ulonglong2 tb = __ldg(&tD[r * HH + h0 + hh]);
            acc[hh] = ffma2(q.x, tb.x, acc[hh]);
            acc[hh] = ffma2(q.y, tb.y, acc[hh]);
        }
    }
#pragma unroll
    for (int hh = 0; hh < 8; hh++) {
        float2 z = upk(acc[hh]);
        g_Z[(size_t)(b * HH + h0 + hh) * 544 + tid] = make_float2(z.x, z.y);
    }
}

// ---------------------------------------------------------------------------
// Stage D2: folded inverse real DFT along W + bias. Block = 2 h rows.
__global__ void __launch_bounds__(256) kD2(const float* __restrict__ bias,
                                           float* __restrict__ y) {
    __shared__ float2 zsm[2 * 544];
    __shared__ float  bs[CC];
    int b  = blockIdx.x >> 7;
    int h0 = (blockIdx.x & 127) << 1;
    int tid = threadIdx.x;
    for (int idx = tid; idx < 2 * 544; idx += 256) {
        int h = idx / 544, s = idx % 544;
        zsm[idx] = g_Z[(size_t)(b * HH + h0 + h) * 544 + s];
    }
    if (tid < CC) bs[tid] = bias[tid];
    __syncthreads();
    int o = tid & 31, ws = tid >> 5;
    u64 z0[EM1_], z1[EM1_];
#pragma unroll
    for (int kw = 0; kw < EM1_; kw++) {
        z0[kw] = *(const u64*)&zsm[kw * CC + o];
        z1[kw] = *(const u64*)&zsm[544 + kw * CC + o];
    }
    float bo = bs[o];
    float* y0 = y + (size_t)(b * HH + h0) * WW * CC;
    float* y1 = y0 + WW * CC;
    const u64* tD2 = (const u64*)g_tD2;
    int niter = (ws == 0) ? 17 : 16;
    for (int j = 0; j < niter; j++) {
        int wp = (j == 16) ? 128 : ws * 16 + j;
        u64 c0 = 0ull, c1 = 0ull;
#pragma unroll
        for (int kw = 0; kw < EM1_; kw++) {
            u64 t = __ldg(&tD2[wp * EM1_ + kw]);
            c0 = ffma2(z0[kw], t, c0);
            c1 = ffma2(z1[kw], t, c1);
        }
        float2 f0 = upk(c0), f1 = upk(c1);
        y0[wp * CC + o] = bo + f0.x - f0.y;
        y1[wp * CC + o] = bo + f1.x - f1.y;
        if (wp > 0 && wp < 128) {
            y0[(256 - wp) * CC + o] = bo + f0.x + f0.y;
            y1[(256 - wp) * CC + o] = bo + f1.x + f1.y;
        }
    }
}

// ---------------------------------------------------------------------------
extern "C" void kernel_launch(void* const* d_in, const int* in_sizes, int n_in,
                              void* d_out, int out_size) {
    const float* x    = (const float*)d_in[0];
    const float* w1r  = (const float*)d_in[1];
    const float* w1i  = (const float*)d_in[2];
    const float* w2r  = (const float*)d_in[3];
    const float* w2i  = (const float*)d_in[4];
    const float* bias = (const float*)d_in[5];
    float* y = (float*)d_out;

    cudaFuncSetAttribute(kA,  cudaFuncAttributeMaxDynamicSharedMemorySize, 65536);
    cudaFuncSetAttribute(kB,  cudaFuncAttributeMaxDynamicSharedMemorySize, 65024);
    cudaFuncSetAttribute(kD1, cudaFuncAttributeMaxDynamicSharedMemorySize, 147968);

    k_init<<<51, 256>>>();
    k_wt<<<(NKH * EM1_ * CC * CC + 255) / 256, 256>>>(w1r, w1i, w2r, w2i);
    kA <<<BB * HH / 2, 80, 65536>>>(x);
    kB <<<BB * EM1_, 256, 65024>>>();
    kC <<<BB * NKH, 544>>>();
    kD1<<<BB * HH / 8, 544, 147968>>>();
    kD2<<<BB * HH / 2, 256>>>(bias, y);
}

// round 6
// speedup vs baseline: 1.7235x; 1.3527x over previous
#include <cuda_runtime.h>

#define BB   16
#define HH   256
#define WW   256
#define CC   32
#define EM0_ 16
#define EM1_ 17
#define NKH  32

typedef unsigned long long u64;

__device__ __forceinline__ u64 ffma2(u64 a, u64 b, u64 c) {
    u64 d;
    asm("fma.rn.f32x2 %0, %1, %2, %3;" : "=l"(d) : "l"(a), "l"(b), "l"(c));
    return d;
}
__device__ __forceinline__ float2 upk(u64 v) {
    float2 r;
    asm("mov.b64 {%0,%1}, %2;" : "=f"(r.x), "=f"(r.y) : "l"(v));
    return r;
}
__device__ __forceinline__ u64 pk(float x, float y) {
    u64 v;
    asm("mov.b64 %0, {%1,%2};" : "=l"(v) : "f"(x), "f"(y));
    return v;
}

// ---- twiddle tables (pair-packed float4 = ulonglong2 for LDS.128) ----
__device__ float4 g_tA2 [128 * 9];   // [wp][binpair]  (c0,-s0, c1,-s1)
__device__ float4 g_tB8 [16 * 128];  // [khpair][hp]   (c0,s0, c1,s1)  m signed
__device__ float4 g_tD1p[17 * 128];  // [r][hpair]     (c(h even),s, c(h odd),s)
__device__ float4 g_tD2p[129 * 9];   // [wp][kwpair]   (c0,s0, c1,s1)

// ---- scratch ----
__device__ float2 g_Xw[BB * HH * EM1_ * CC];       // after W-DFT
__device__ float2 g_Xm[BB * NKH * EM1_ * CC];      // after H-DFT
__device__ float2 g_Md[BB * NKH * EM1_ * CC];      // after mixing (x2 folded)
__device__ float4 g_SD[BB * EM1_ * EM1_ * CC];     // folded Md: (S.x,-D.y,S.y,D.x)
__device__ float4 g_wT2[NKH * EM1_ * CC * CC];     // ((wr,wi),(-wi,wr))

// ---------------------------------------------------------------------------
__global__ void k_init() {
    int idx = blockIdx.x * 256 + threadIdx.x;
    if (idx < 1152) {                         // g_tA2
        int wp = idx / 9, bp = idx % 9;
        int b0 = 2 * bp, b1 = 2 * bp + 1;
        float s0, c0, s1 = 0.f, c1 = 0.f;
        sincospif((float)((b0 * wp) & 255) / 128.f, &s0, &c0);
        if (b1 <= 16) sincospif((float)((b1 * wp) & 255) / 128.f, &s1, &c1);
        g_tA2[idx] = make_float4(c0, -s0, c1, -s1);
    }
    int j = idx - 1152;
    if (j >= 0 && j < 2048) {                 // g_tB8
        int kp = j >> 7, hp = j & 127;
        int kh0 = 2 * kp, kh1 = 2 * kp + 1;
        int m0 = (kh0 < EM0_) ? kh0 : kh0 - NKH;
        int m1 = (kh1 < EM0_) ? kh1 : kh1 - NKH;
        float s0, c0, s1, c1;
        sincospif((float)((m0 * hp) & 255) / 128.f, &s0, &c0);
        sincospif((float)((m1 * hp) & 255) / 128.f, &s1, &c1);
        g_tB8[j] = make_float4(c0, s0, c1, s1);
    }
    int e = j - 2048;
    if (e >= 0 && e < 2176) {                 // g_tD1p
        int r = e >> 7, hpi = e & 127;
        int m = (r < 16) ? r : -16;
        int h0 = 2 * hpi, h1 = 2 * hpi + 1;
        float s0, c0, s1, c1;
        sincospif((float)((m * h0) & 255) / 128.f, &s0, &c0);
        sincospif((float)((m * h1) & 255) / 128.f, &s1, &c1);
        g_tD1p[e] = make_float4(c0, s0, c1, s1);
    }
    int f = e - 2176;
    if (f >= 0 && f < 1161) {                 // g_tD2p
        int wp = f / 9, kp = f % 9;
        int k0 = 2 * kp, k1 = 2 * kp + 1;
        float s0, c0, s1 = 0.f, c1 = 0.f;
        sincospif((float)((k0 * wp) & 255) / 128.f, &s0, &c0);
        if (k1 <= 16) sincospif((float)((k1 * wp) & 255) / 128.f, &s1, &c1);
        g_tD2p[f] = make_float4(c0, s0, c1, s1);
    }
}

// ---------------------------------------------------------------------------
__global__ void k_wt2(const float* __restrict__ w1r, const float* __restrict__ w1i,
                      const float* __restrict__ w2r, const float* __restrict__ w2i) {
    int idx = blockIdx.x * blockDim.x + threadIdx.x;
    if (idx >= NKH * EM1_ * CC * CC) return;
    int o = idx & 31;
    int t = idx >> 5;
    int i = t & 31; t >>= 5;
    int kw = t % EM1_;
    int kh = t / EM1_;
    int khm = (kh < EM0_) ? kh : kh - EM0_;
    const float* wr = (kh < EM0_) ? w1r : w2r;
    const float* wi = (kh < EM0_) ? w1i : w2i;
    int s = ((i * CC + o) * EM0_ + khm) * EM1_ + kw;
    float vr = wr[s], vi = wi[s];
    g_wT2[((kh * EM1_ + kw) * CC + i) * CC + o] = make_float4(vr, vi, -vi, vr);
}

// ---------------------------------------------------------------------------
// Stage A: folded partial real DFT along W. Block = 2 h rows, 128 threads
// = (ipair16, h2, wq4). Each thread: all 17 bins, 2 channels, 32 w'-pairs.
// Partial results reduced across the 4 wq slices through smem.
__global__ void __launch_bounds__(128) kA(const float* __restrict__ x) {
    extern __shared__ char smA[];
    ulonglong2* sd = (ulonglong2*)smA;              // [h][wp][ip] 64KB
    ulonglong2* tw = (ulonglong2*)(smA + 65536);    // [wp][bp]    18KB
    u64*      red = (u64*)smA;                      // reused after sync (4*1088 u64)

    int b = blockIdx.x >> 7, h0 = (blockIdx.x & 127) << 1;
    const float* xb = x + ((size_t)(b * HH + h0)) * (WW * CC);
    int tid = threadIdx.x;

    for (int t = tid; t < 128 * 9; t += 128)
        tw[t] = ((const ulonglong2*)g_tA2)[t];
    for (int p = tid; p < 2048; p += 128) {
        int wp = p >> 4, c4 = p & 15, h = c4 >> 3, ch = c4 & 7;
        int partner = wp ? (256 - wp) : 128;
        float4 a = *(const float4*)&xb[h * (WW * CC) + wp * CC + ch * 4];
        float4 e = *(const float4*)&xb[h * (WW * CC) + partner * CC + ch * 4];
        float4* dst = (float4*)sd;
        int base = (h * 128 + wp) * 16 + ch * 2;
        dst[base    ] = make_float4(a.x + e.x, a.x - e.x, a.y + e.y, a.y - e.y);
        dst[base + 1] = make_float4(a.z + e.z, a.z - e.z, a.w + e.w, a.w - e.w);
    }
    __syncthreads();

    int ip = tid & 15, h = (tid >> 4) & 1, wq = tid >> 5;
    u64 acc[18][2];
#pragma unroll
    for (int bb = 0; bb < 18; bb++) { acc[bb][0] = 0ull; acc[bb][1] = 0ull; }
    if (wq == 0) {   // w'=0 boundary: re = S for even bins, D for odd; im = 0
        ulonglong2 q0 = sd[(h * 128) * 16 + ip];
        float2 v0 = upk(q0.x), v1 = upk(q0.y);
#pragma unroll
        for (int bb = 0; bb < 17; bb++) {
            acc[bb][0] = pk((bb & 1) ? v0.y : v0.x, 0.f);
            acc[bb][1] = pk((bb & 1) ? v1.y : v1.x, 0.f);
        }
    }
    int w_lo = (wq == 0) ? 1 : wq * 32;
    int w_hi = wq * 32 + 32;
    for (int wp = w_lo; wp < w_hi; wp++) {
        ulonglong2 q = sd[(h * 128 + wp) * 16 + ip];
#pragma unroll
        for (int bp = 0; bp < 9; bp++) {
            ulonglong2 t = tw[wp * 9 + bp];
            acc[2*bp  ][0] = ffma2(q.x, t.x, acc[2*bp  ][0]);
            acc[2*bp  ][1] = ffma2(q.y, t.x, acc[2*bp  ][1]);
            acc[2*bp+1][0] = ffma2(q.x, t.y, acc[2*bp+1][0]);
            acc[2*bp+1][1] = ffma2(q.y, t.y, acc[2*bp+1][1]);
        }
    }
    __syncthreads();
    // one u64 (re,im) per (h, bin, channel): 2*17*32 = 1088 per wq slice
#pragma unroll
    for (int bb = 0; bb < 17; bb++) {
        red[wq * 1088 + ((h * 17 + bb) * 16 + ip) * 2    ] = acc[bb][0];
        red[wq * 1088 + ((h * 17 + bb) * 16 + ip) * 2 + 1] = acc[bb][1];
    }
    __syncthreads();
    const float sc = 1.f / 65536.f;
    for (int s = tid; s < 1088; s += 128) {
        float2 a0 = upk(red[s]),          a1 = upk(red[1088 + s]);
        float2 a2 = upk(red[2*1088 + s]), a3 = upk(red[3*1088 + s]);
        float re = (a0.x + a1.x) + (a2.x + a3.x);
        float im = (a0.y + a1.y) + (a2.y + a3.y);
        int chi = s & 1, t2 = s >> 1;
        int ipp = t2 & 15, t3 = t2 >> 4;   // t3 in 0..33
        int bb = t3 % 17, hh = t3 / 17;    // hh in 0..1
        g_Xw[((size_t)(b * HH + h0 + hh) * EM1_ + bb) * CC + ipp * 2 + chi]
            = make_float2(re * sc, im * sc);
    }
}

// ---------------------------------------------------------------------------
// Stage B: folded complex DFT along H. Block=(b,kw), 128 thr = (i32, kg4 of 8 kh).
__global__ void __launch_bounds__(128) kB() {
    extern __shared__ char smB[];
    ulonglong2* sdB = (ulonglong2*)smB;              // [hp-1][i]: ((Sx,Dy),(Sy,-Dx))
    ulonglong2* twB = (ulonglong2*)(smB + 65024);    // [khpair][hp]
    int b = blockIdx.x / EM1_, kw = blockIdx.x % EM1_;
    int tid = threadIdx.x;
    for (int t = tid; t < 16 * 128; t += 128)
        twB[t] = ((const ulonglong2*)g_tB8)[t];
    for (int idx = tid; idx < 127 * 32; idx += 128) {
        int hp = (idx >> 5) + 1, i = idx & 31;
        float2 v  = g_Xw[((size_t)(b * HH + hp) * EM1_ + kw) * CC + i];
        float2 vp = g_Xw[((size_t)(b * HH + 256 - hp) * EM1_ + kw) * CC + i];
        ((float4*)sdB)[idx] = make_float4(v.x + vp.x, v.y - vp.y,
                                          v.y + vp.y, -(v.x - vp.x));
    }
    __syncthreads();
    int i = tid & 31, kg = tid >> 5;
    float2 v0  = g_Xw[((size_t)(b * HH)       * EM1_ + kw) * CC + i];
    float2 v12 = g_Xw[((size_t)(b * HH + 128) * EM1_ + kw) * CC + i];
    u64 accA[8], accB[8];
#pragma unroll
    for (int t = 0; t < 8; t++) {
        float p = ((kg * 8 + t) & 1) ? -1.f : 1.f;
        accA[t] = pk(v0.x + p * v12.x, 0.f);
        accB[t] = pk(v0.y + p * v12.y, 0.f);
    }
    for (int hp = 1; hp < 128; hp++) {
        ulonglong2 q = sdB[(hp - 1) * 32 + i];
#pragma unroll
        for (int j = 0; j < 4; j++) {
            ulonglong2 t = twB[(kg * 4 + j) * 128 + hp];
            accA[2*j  ] = ffma2(q.x, t.x, accA[2*j  ]);
            accB[2*j  ] = ffma2(q.y, t.x, accB[2*j  ]);
            accA[2*j+1] = ffma2(q.x, t.y, accA[2*j+1]);
            accB[2*j+1] = ffma2(q.y, t.y, accB[2*j+1]);
        }
    }
#pragma unroll
    for (int t = 0; t < 8; t++) {
        float2 ra = upk(accA[t]), rb = upk(accB[t]);
        g_Xm[((size_t)(b * NKH + kg * 8 + t) * EM1_ + kw) * CC + i]
            = make_float2(ra.x + ra.y, rb.x + rb.y);
    }
}

// ---------------------------------------------------------------------------
// Stage C: channel mixing. Block=(kw, khgrp of 4); weights in smem, loop all b.
__global__ void __launch_bounds__(256) kC() {
    extern __shared__ char smC[];
    ulonglong2* ws = (ulonglong2*)smC;              // [khl4][i][o] 64KB
    float2*     xs = (float2*)(smC + 65536);        // [b16][khl4][i] 16KB
    int kw = blockIdx.x / 8, khg = blockIdx.x % 8;
    int tid = threadIdx.x;
    for (int t = tid; t < 4096; t += 256) {
        int khl = t >> 10, rem = t & 1023, i = rem >> 5, o = rem & 31;
        ws[t] = ((const ulonglong2*)g_wT2)
                    [(((khg * 4 + khl) * EM1_ + kw) * CC + i) * CC + o];
    }
    for (int t = tid; t < 2048; t += 256) {
        int b = t >> 7, rem = t & 127, khl = rem >> 5, i = rem & 31;
        xs[t] = g_Xm[((size_t)(b * NKH + khg * 4 + khl) * EM1_ + kw) * CC + i];
    }
    __syncthreads();
    int o = tid & 31, slot = tid >> 5;
    float f = (kw == 0) ? 1.f : 2.f;
    for (int u = 0; u < 2; u++) {
        int unit = slot * 2 + u;
        int khl = unit >> 2, bq = unit & 3;
        u64 acc[4] = {0ull, 0ull, 0ull, 0ull};
        for (int i = 0; i < CC; i++) {
            ulonglong2 wv = ws[(khl * 32 + i) * 32 + o];
#pragma unroll
            for (int bb = 0; bb < 4; bb++) {
                float2 xv = xs[((bq * 4 + bb) * 4 + khl) * 32 + i];
                acc[bb] = ffma2(pk(xv.x, xv.x), wv.x, acc[bb]);
                acc[bb] = ffma2(pk(xv.y, xv.y), wv.y, acc[bb]);
            }
        }
#pragma unroll
        for (int bb = 0; bb < 4; bb++) {
            float2 r = upk(acc[bb]);
            g_Md[((size_t)((bq * 4 + bb) * NKH + khg * 4 + khl)) * 544
                 + kw * 32 + o] = make_float2(r.x * f, r.y * f);
        }
    }
}

// ---------------------------------------------------------------------------
// kSD: fold Md over +-kh pairs -> (S.x, -D.y, S.y, D.x)
__global__ void __launch_bounds__(544) kSD() {
    int b = blockIdx.x / EM1_, r = blockIdx.x % EM1_;
    int tid = threadIdx.x;
    float2 m1 = g_Md[(size_t)(b * NKH + r) * 544 + tid];
    float2 S, D;
    if (r >= 1 && r <= 15) {
        float2 m2 = g_Md[(size_t)(b * NKH + 32 - r) * 544 + tid];
        S = make_float2(m1.x + m2.x, m1.y + m2.y);
        D = make_float2(m1.x - m2.x, m1.y - m2.y);
    } else { S = m1; D = m1; }
    g_SD[(size_t)(b * EM1_ + r) * 544 + tid] = make_float4(S.x, -D.y, S.y, D.x);
}

// ---------------------------------------------------------------------------
// kD: fused inverse H-DFT + inverse real W-DFT + bias. Block = 8 h rows, 544 thr.
__global__ void __launch_bounds__(544) kD(const float* __restrict__ bias,
                                          float* __restrict__ y) {
    extern __shared__ char smD[];
    float2*     zsm = (float2*)smD;                  // [8][544] 34KB
    ulonglong2* t2s = (ulonglong2*)(smD + 34816);    // [wp][kwpair] 18.6KB
    float*      bs  = (float*)(smD + 34816 + 18576);
    int b = blockIdx.x >> 5, h0 = (blockIdx.x & 31) << 3;
    int tid = threadIdx.x;
    for (int t = tid; t < 129 * 9; t += 544)
        t2s[t] = ((const ulonglong2*)g_tD2p)[t];
    if (tid < CC) bs[tid] = bias[tid];
    // phase 1: Z for 8 h rows
    {
        u64 aA[8], aB[8];
#pragma unroll
        for (int hh = 0; hh < 8; hh++) { aA[hh] = 0ull; aB[hh] = 0ull; }
        const ulonglong2* SDp =
            (const ulonglong2*)g_SD + (size_t)b * EM1_ * 544 + tid;
        const ulonglong2* tbase =
            (const ulonglong2*)g_tD1p + (h0 >> 1);
        for (int r = 0; r < 17; r++) {
            ulonglong2 q = SDp[r * 544];
#pragma unroll
            for (int jp = 0; jp < 4; jp++) {
                ulonglong2 t = __ldg(&tbase[r * 128 + jp]);
                aA[2*jp  ] = ffma2(q.x, t.x, aA[2*jp  ]);
                aB[2*jp  ] = ffma2(q.y, t.x, aB[2*jp  ]);
                aA[2*jp+1] = ffma2(q.x, t.y, aA[2*jp+1]);
                aB[2*jp+1] = ffma2(q.y, t.y, aB[2*jp+1]);
            }
        }
#pragma unroll
        for (int hh = 0; hh < 8; hh++) {
            float2 ra = upk(aA[hh]), rb = upk(aB[hh]);
            zsm[hh * 544 + tid] = make_float2(ra.x + ra.y, rb.x + rb.y);
        }
    }
    __syncthreads();
    // phase 2: inverse real W-DFT, 2 h rows per pass
    int o = tid & 31, ws = tid >> 5;
    float bo = bs[o];
    for (int hp = 0; hp < 4; hp++) {
        u64 z0[17], z1[17];
#pragma unroll
        for (int kw = 0; kw < 17; kw++) {
            z0[kw] = *(const u64*)&zsm[(2 * hp    ) * 544 + kw * 32 + o];
            z1[kw] = *(const u64*)&zsm[(2 * hp + 1) * 544 + kw * 32 + o];
        }
        float* y0 = y + (size_t)(b * HH + h0 + 2 * hp) * WW * CC;
        float* y1 = y0 + WW * CC;
        int niter = (ws == 16) ? 1 : 8;
        for (int j = 0; j < niter; j++) {
            int wp = (ws == 16) ? 128 : ws * 8 + j;
            u64 c0 = 0ull, c1 = 0ull;
#pragma unroll
            for (int kp = 0; kp < 8; kp++) {
                ulonglong2 t = t2s[wp * 9 + kp];
                c0 = ffma2(z0[2*kp], t.x, c0); c0 = ffma2(z0[2*kp+1], t.y, c0);
                c1 = ffma2(z1[2*kp], t.x, c1); c1 = ffma2(z1[2*kp+1], t.y, c1);
            }
            {
                ulonglong2 t = t2s[wp * 9 + 8];
                c0 = ffma2(z0[16], t.x, c0);
                c1 = ffma2(z1[16], t.x, c1);
            }
            float2 f0 = upk(c0), f1 = upk(c1);
            y0[wp * CC + o] = bo + f0.x - f0.y;
            y1[wp * CC + o] = bo + f1.x - f1.y;
            if (wp > 0 && wp < 128) {
                y0[(256 - wp) * CC + o] = bo + f0.x + f0.y;
                y1[(256 - wp) * CC + o] = bo + f1.x + f1.y;
            }
        }
    }
}

// ---------------------------------------------------------------------------
extern "C" void kernel_launch(void* const* d_in, const int* in_sizes, int n_in,
                              void* d_out, int out_size) {
    const float* x    = (const float*)d_in[0];
    const float* w1r  = (const float*)d_in[1];
    const float* w1i  = (const float*)d_in[2];
    const float* w2r  = (const float*)d_in[3];
    const float* w2i  = (const float*)d_in[4];
    const float* bias = (const float*)d_in[5];
    float* y = (float*)d_out;

    cudaFuncSetAttribute(kA, cudaFuncAttributeMaxDynamicSharedMemorySize, 83968);
    cudaFuncSetAttribute(kB, cudaFuncAttributeMaxDynamicSharedMemorySize, 97792);
    cudaFuncSetAttribute(kC, cudaFuncAttributeMaxDynamicSharedMemorySize, 81920);
    cudaFuncSetAttribute(kD, cudaFuncAttributeMaxDynamicSharedMemorySize, 53520);

    k_init<<<26, 256>>>();
    k_wt2<<<(NKH * EM1_ * CC * CC + 255) / 256, 256>>>(w1r, w1i, w2r, w2i);
    kA <<<BB * HH / 2, 128, 83968>>>(x);
    kB <<<BB * EM1_, 128, 97792>>>();
    kC <<<EM1_ * 8, 256, 81920>>>();
    kSD<<<BB * EM1_, 544>>>();
    kD <<<BB * HH / 8, 544, 53520>>>(bias, y);
}

// round 8
// speedup vs baseline: 2.0583x; 1.1942x over previous
#include <cuda_runtime.h>

#define BB   16
#define HH   256
#define WW   256
#define CC   32
#define EM0_ 16
#define EM1_ 17
#define NKH  32

typedef unsigned long long u64;

__device__ __forceinline__ u64 ffma2(u64 a, u64 b, u64 c) {
    u64 d;
    asm("fma.rn.f32x2 %0, %1, %2, %3;" : "=l"(d) : "l"(a), "l"(b), "l"(c));
    return d;
}
__device__ __forceinline__ float2 upk(u64 v) {
    float2 r;
    asm("mov.b64 {%0,%1}, %2;" : "=f"(r.x), "=f"(r.y) : "l"(v));
    return r;
}
__device__ __forceinline__ u64 pk(float x, float y) {
    u64 v;
    asm("mov.b64 %0, {%1,%2};" : "=l"(v) : "f"(x), "f"(y));
    return v;
}

// ---- twiddle tables (pair-packed float4 = ulonglong2 for LDS.128) ----
__device__ float4 g_tA2 [128 * 9];   // [wp][binpair]  (c0,-s0, c1,-s1)
__device__ float4 g_tB8 [16 * 128];  // [khpair][hp]   (c0,s0, c1,s1)  m signed
__device__ float4 g_tD1p[17 * 128];  // [r][hpair]     (c(h even),s, c(h odd),s)
__device__ float4 g_tD2p[129 * 9];   // [wp][kwpair]   (c0,s0, c1,s1)

// ---- scratch ----
__device__ float2 g_Xw[BB * HH * EM1_ * CC];       // after W-DFT
__device__ float2 g_Xm[BB * NKH * EM1_ * CC];      // after H-DFT
__device__ float2 g_Md[BB * NKH * EM1_ * CC];      // after mixing (x2 folded)
__device__ float4 g_SD[BB * EM1_ * EM1_ * CC];     // folded Md: (S.x,-D.y,S.y,D.x)
__device__ float4 g_wT2[NKH * EM1_ * CC * CC];     // ((wr,wi),(-wi,wr))

// ---------------------------------------------------------------------------
__global__ void k_init() {
    int idx = blockIdx.x * 256 + threadIdx.x;
    if (idx < 1152) {                         // g_tA2
        int wp = idx / 9, bp = idx % 9;
        int b0 = 2 * bp, b1 = 2 * bp + 1;
        float s0, c0, s1 = 0.f, c1 = 0.f;
        sincospif((float)((b0 * wp) & 255) / 128.f, &s0, &c0);
        if (b1 <= 16) sincospif((float)((b1 * wp) & 255) / 128.f, &s1, &c1);
        g_tA2[idx] = make_float4(c0, -s0, c1, -s1);
    }
    int j = idx - 1152;
    if (j >= 0 && j < 2048) {                 // g_tB8
        int kp = j >> 7, hp = j & 127;
        int kh0 = 2 * kp, kh1 = 2 * kp + 1;
        int m0 = (kh0 < EM0_) ? kh0 : kh0 - NKH;
        int m1 = (kh1 < EM0_) ? kh1 : kh1 - NKH;
        float s0, c0, s1, c1;
        sincospif((float)((m0 * hp) & 255) / 128.f, &s0, &c0);
        sincospif((float)((m1 * hp) & 255) / 128.f, &s1, &c1);
        g_tB8[j] = make_float4(c0, s0, c1, s1);
    }
    int e = j - 2048;
    if (e >= 0 && e < 2176) {                 // g_tD1p
        int r = e >> 7, hpi = e & 127;
        int m = (r < 16) ? r : -16;
        int h0 = 2 * hpi, h1 = 2 * hpi + 1;
        float s0, c0, s1, c1;
        sincospif((float)((m * h0) & 255) / 128.f, &s0, &c0);
        sincospif((float)((m * h1) & 255) / 128.f, &s1, &c1);
        g_tD1p[e] = make_float4(c0, s0, c1, s1);
    }
    int f = e - 2176;
    if (f >= 0 && f < 1161) {                 // g_tD2p
        int wp = f / 9, kp = f % 9;
        int k0 = 2 * kp, k1 = 2 * kp + 1;
        float s0, c0, s1 = 0.f, c1 = 0.f;
        sincospif((float)((k0 * wp) & 255) / 128.f, &s0, &c0);
        if (k1 <= 16) sincospif((float)((k1 * wp) & 255) / 128.f, &s1, &c1);
        g_tD2p[f] = make_float4(c0, s0, c1, s1);
    }
}

// ---------------------------------------------------------------------------
__global__ void k_wt2(const float* __restrict__ w1r, const float* __restrict__ w1i,
                      const float* __restrict__ w2r, const float* __restrict__ w2i) {
    int idx = blockIdx.x * blockDim.x + threadIdx.x;
    if (idx >= NKH * EM1_ * CC * CC) return;
    int o = idx & 31;
    int t = idx >> 5;
    int i = t & 31; t >>= 5;
    int kw = t % EM1_;
    int kh = t / EM1_;
    int khm = (kh < EM0_) ? kh : kh - EM0_;
    const float* wr = (kh < EM0_) ? w1r : w2r;
    const float* wi = (kh < EM0_) ? w1i : w2i;
    int s = ((i * CC + o) * EM0_ + khm) * EM1_ + kw;
    float vr = wr[s], vi = wi[s];
    g_wT2[((kh * EM1_ + kw) * CC + i) * CC + o] = make_float4(vr, vi, -vi, vr);
}

// ---------------------------------------------------------------------------
// Stage A: folded partial real DFT along W. Block = 2 h rows, 256 threads
// = (ipair16, h2, wq8). Each thread: all 17 bins, 2 channels, 16 w'-pairs.
// Partial results reduced across the 8 wq slices through smem.
__global__ void __launch_bounds__(256) kA(const float* __restrict__ x) {
    extern __shared__ char smA[];
    ulonglong2* sd = (ulonglong2*)smA;              // [h][wp][ip] 64KB
    ulonglong2* tw = (ulonglong2*)(smA + 65536);    // [wp][bp]    18KB
    u64*      red = (u64*)smA;                      // reused after sync (8*1088 u64)

    int b = blockIdx.x >> 7, h0 = (blockIdx.x & 127) << 1;
    const float* xb = x + ((size_t)(b * HH + h0)) * (WW * CC);
    int tid = threadIdx.x;

    for (int t = tid; t < 128 * 9; t += 256)
        tw[t] = ((const ulonglong2*)g_tA2)[t];
    for (int p = tid; p < 2048; p += 256) {
        int wp = p >> 4, c4 = p & 15, h = c4 >> 3, ch = c4 & 7;
        int partner = wp ? (256 - wp) : 128;
        float4 a = *(const float4*)&xb[h * (WW * CC) + wp * CC + ch * 4];
        float4 e = *(const float4*)&xb[h * (WW * CC) + partner * CC + ch * 4];
        float4* dst = (float4*)sd;
        int base = (h * 128 + wp) * 16 + ch * 2;
        dst[base    ] = make_float4(a.x + e.x, a.x - e.x, a.y + e.y, a.y - e.y);
        dst[base + 1] = make_float4(a.z + e.z, a.z - e.z, a.w + e.w, a.w - e.w);
    }
    __syncthreads();

    int ip = tid & 15, h = (tid >> 4) & 1, wq = tid >> 5;  // wq 0..7
    u64 acc[18][2];
#pragma unroll
    for (int bb = 0; bb < 18; bb++) { acc[bb][0] = 0ull; acc[bb][1] = 0ull; }
    if (wq == 0) {   // w'=0 boundary: re = S for even bins, D for odd; im = 0
        ulonglong2 q0 = sd[(h * 128) * 16 + ip];
        float2 v0 = upk(q0.x), v1 = upk(q0.y);
#pragma unroll
        for (int bb = 0; bb < 17; bb++) {
            acc[bb][0] = pk((bb & 1) ? v0.y : v0.x, 0.f);
            acc[bb][1] = pk((bb & 1) ? v1.y : v1.x, 0.f);
        }
    }
    int w_lo = (wq == 0) ? 1 : wq * 16;
    int w_hi = wq * 16 + 16;
    for (int wp = w_lo; wp < w_hi; wp++) {
        ulonglong2 q = sd[(h * 128 + wp) * 16 + ip];
#pragma unroll
        for (int bp = 0; bp < 9; bp++) {
            ulonglong2 t = tw[wp * 9 + bp];
            acc[2*bp  ][0] = ffma2(q.x, t.x, acc[2*bp  ][0]);
            acc[2*bp  ][1] = ffma2(q.y, t.x, acc[2*bp  ][1]);
            acc[2*bp+1][0] = ffma2(q.x, t.y, acc[2*bp+1][0]);
            acc[2*bp+1][1] = ffma2(q.y, t.y, acc[2*bp+1][1]);
        }
    }
    __syncthreads();
    // one u64 (re,im) per (h, bin, channel): 2*17*32 = 1088 per wq slice
#pragma unroll
    for (int bb = 0; bb < 17; bb++) {
        red[wq * 1088 + ((h * 17 + bb) * 16 + ip) * 2    ] = acc[bb][0];
        red[wq * 1088 + ((h * 17 + bb) * 16 + ip) * 2 + 1] = acc[bb][1];
    }
    __syncthreads();
    const float sc = 1.f / 65536.f;
    for (int s = tid; s < 1088; s += 256) {
        float re = 0.f, im = 0.f;
#pragma unroll
        for (int k = 0; k < 8; k++) {
            float2 a = upk(red[k * 1088 + s]);
            re += a.x; im += a.y;
        }
        int chi = s & 1, t2 = s >> 1;
        int ipp = t2 & 15, t3 = t2 >> 4;   // t3 in 0..33
        int bb = t3 % 17, hh = t3 / 17;    // hh in 0..1
        g_Xw[((size_t)(b * HH + h0 + hh) * EM1_ + bb) * CC + ipp * 2 + chi]
            = make_float2(re * sc, im * sc);
    }
}

// ---------------------------------------------------------------------------
// Stage B: folded complex DFT along H. Block=(b,kw), 256 thr = (i32, kg8 of 4 kh).
// Twiddles via __ldg broadcast (warp-uniform index) -> smem only for data fold.
__global__ void __launch_bounds__(256) kB() {
    extern __shared__ char smB[];
    ulonglong2* sdB = (ulonglong2*)smB;    // [hp-1][i]: ((Sx,Dy),(Sy,-Dx)) 65KB
    int b = blockIdx.x / EM1_, kw = blockIdx.x % EM1_;
    int tid = threadIdx.x;
    for (int idx = tid; idx < 127 * 32; idx += 256) {
        int hp = (idx >> 5) + 1, i = idx & 31;
        float2 v  = g_Xw[((size_t)(b * HH + hp) * EM1_ + kw) * CC + i];
        float2 vp = g_Xw[((size_t)(b * HH + 256 - hp) * EM1_ + kw) * CC + i];
        ((float4*)sdB)[idx] = make_float4(v.x + vp.x, v.y - vp.y,
                                          v.y + vp.y, -(v.x - vp.x));
    }
    __syncthreads();
    int i = tid & 31, kg = tid >> 5;   // kg 0..7, 4 kh each
    float2 v0  = g_Xw[((size_t)(b * HH)       * EM1_ + kw) * CC + i];
    float2 v12 = g_Xw[((size_t)(b * HH + 128) * EM1_ + kw) * CC + i];
    u64 accA[4], accB[4];
#pragma unroll
    for (int t = 0; t < 4; t++) {
        float p = ((kg * 4 + t) & 1) ? -1.f : 1.f;
        accA[t] = pk(v0.x + p * v12.x, 0.f);
        accB[t] = pk(v0.y + p * v12.y, 0.f);
    }
    const ulonglong2* tB = (const ulonglong2*)g_tB8;
#pragma unroll 4
    for (int hp = 1; hp < 128; hp++) {
        ulonglong2 q  = sdB[(hp - 1) * 32 + i];
        ulonglong2 t0 = __ldg(&tB[(kg * 2    ) * 128 + hp]);
        ulonglong2 t1 = __ldg(&tB[(kg * 2 + 1) * 128 + hp]);
        accA[0] = ffma2(q.x, t0.x, accA[0]); accB[0] = ffma2(q.y, t0.x, accB[0]);
        accA[1] = ffma2(q.x, t0.y, accA[1]); accB[1] = ffma2(q.y, t0.y, accB[1]);
        accA[2] = ffma2(q.x, t1.x, accA[2]); accB[2] = ffma2(q.y, t1.x, accB[2]);
        accA[3] = ffma2(q.x, t1.y, accA[3]); accB[3] = ffma2(q.y, t1.y, accB[3]);
    }
#pragma unroll
    for (int t = 0; t < 4; t++) {
        float2 ra = upk(accA[t]), rb = upk(accB[t]);
        g_Xm[((size_t)(b * NKH + kg * 4 + t) * EM1_ + kw) * CC + i]
            = make_float2(ra.x + ra.y, rb.x + rb.y);
    }
}

// ---------------------------------------------------------------------------
// Stage C: channel mixing. Block=(kw, khgrp of 4); weights in smem, loop all b.
__global__ void __launch_bounds__(256) kC() {
    extern __shared__ char smC[];
    ulonglong2* ws = (ulonglong2*)smC;              // [khl4][i][o] 64KB
    float2*     xs = (float2*)(smC + 65536);        // [b16][khl4][i] 16KB
    int kw = blockIdx.x / 8, khg = blockIdx.x % 8;
    int tid = threadIdx.x;
    for (int t = tid; t < 4096; t += 256) {
        int khl = t >> 10, rem = t & 1023, i = rem >> 5, o = rem & 31;
        ws[t] = ((const ulonglong2*)g_wT2)
                    [(((khg * 4 + khl) * EM1_ + kw) * CC + i) * CC + o];
    }
    for (int t = tid; t < 2048; t += 256) {
        int b = t >> 7, rem = t & 127, khl = rem >> 5, i = rem & 31;
        xs[t] = g_Xm[((size_t)(b * NKH + khg * 4 + khl) * EM1_ + kw) * CC + i];
    }
    __syncthreads();
    int o = tid & 31, slot = tid >> 5;
    float f = (kw == 0) ? 1.f : 2.f;
    for (int u = 0; u < 2; u++) {
        int unit = slot * 2 + u;
        int khl = unit >> 2, bq = unit & 3;
        u64 acc[4] = {0ull, 0ull, 0ull, 0ull};
        for (int i = 0; i < CC; i++) {
            ulonglong2 wv = ws[(khl * 32 + i) * 32 + o];
#pragma unroll
            for (int bb = 0; bb < 4; bb++) {
                float2 xv = xs[((bq * 4 + bb) * 4 + khl) * 32 + i];
                acc[bb] = ffma2(pk(xv.x, xv.x), wv.x, acc[bb]);
                acc[bb] = ffma2(pk(xv.y, xv.y), wv.y, acc[bb]);
            }
        }
#pragma unroll
        for (int bb = 0; bb < 4; bb++) {
            float2 r = upk(acc[bb]);
            g_Md[((size_t)((bq * 4 + bb) * NKH + khg * 4 + khl)) * 544
                 + kw * 32 + o] = make_float2(r.x * f, r.y * f);
        }
    }
}

// ---------------------------------------------------------------------------
// kSD: fold Md over +-kh pairs -> (S.x, -D.y, S.y, D.x)
__global__ void __launch_bounds__(544) kSD() {
    int b = blockIdx.x / EM1_, r = blockIdx.x % EM1_;
    int tid = threadIdx.x;
    float2 m1 = g_Md[(size_t)(b * NKH + r) * 544 + tid];
    float2 S, D;
    if (r >= 1 && r <= 15) {
        float2 m2 = g_Md[(size_t)(b * NKH + 32 - r) * 544 + tid];
        S = make_float2(m1.x + m2.x, m1.y + m2.y);
        D = make_float2(m1.x - m2.x, m1.y - m2.y);
    } else { S = m1; D = m1; }
    g_SD[(size_t)(b * EM1_ + r) * 544 + tid] = make_float4(S.x, -D.y, S.y, D.x);
}

// ---------------------------------------------------------------------------
// kD: fused inverse H-DFT + inverse real W-DFT + bias. Block = 8 h rows, 544 thr.
__global__ void __launch_bounds__(544) kD(const float* __restrict__ bias,
                                          float* __restrict__ y) {
    extern __shared__ char smD[];
    float2*     zsm = (float2*)smD;                  // [8][544] 34KB
    ulonglong2* t2s = (ulonglong2*)(smD + 34816);    // [wp][kwpair] 18.6KB
    float*      bs  = (float*)(smD + 34816 + 18576);
    int b = blockIdx.x >> 5, h0 = (blockIdx.x & 31) << 3;
    int tid = threadIdx.x;
    for (int t = tid; t < 129 * 9; t += 544)
        t2s[t] = ((const ulonglong2*)g_tD2p)[t];
    if (tid < CC) bs[tid] = bias[tid];
    // phase 1: Z for 8 h rows
    {
        u64 aA[8], aB[8];
#pragma unroll
        for (int hh = 0; hh < 8; hh++) { aA[hh] = 0ull; aB[hh] = 0ull; }
        const ulonglong2* SDp =
            (const ulonglong2*)g_SD + (size_t)b * EM1_ * 544 + tid;
        const ulonglong2* tbase =
            (const ulonglong2*)g_tD1p + (h0 >> 1);
        for (int r = 0; r < 17; r++) {
            ulonglong2 q = SDp[r * 544];
#pragma unroll
            for (int jp = 0; jp < 4; jp++) {
                ulonglong2 t = __ldg(&tbase[r * 128 + jp]);
                aA[2*jp  ] = ffma2(q.x, t.x, aA[2*jp  ]);
                aB[2*jp  ] = ffma2(q.y, t.x, aB[2*jp  ]);
                aA[2*jp+1] = ffma2(q.x, t.y, aA[2*jp+1]);
                aB[2*jp+1] = ffma2(q.y, t.y, aB[2*jp+1]);
            }
        }
#pragma unroll
        for (int hh = 0; hh < 8; hh++) {
            float2 ra = upk(aA[hh]), rb = upk(aB[hh]);
            zsm[hh * 544 + tid] = make_float2(ra.x + ra.y, rb.x + rb.y);
        }
    }
    __syncthreads();
    // phase 2: inverse real W-DFT, 2 h rows per pass
    int o = tid & 31, ws = tid >> 5;
    float bo = bs[o];
    for (int hp = 0; hp < 4; hp++) {
        u64 z0[17], z1[17];
#pragma unroll
        for (int kw = 0; kw < 17; kw++) {
            z0[kw] = *(const u64*)&zsm[(2 * hp    ) * 544 + kw * 32 + o];
            z1[kw] = *(const u64*)&zsm[(2 * hp + 1) * 544 + kw * 32 + o];
        }
        float* y0 = y + (size_t)(b * HH + h0 + 2 * hp) * WW * CC;
        float* y1 = y0 + WW * CC;
        int niter = (ws == 16) ? 1 : 8;
        for (int j = 0; j < niter; j++) {
            int wp = (ws == 16) ? 128 : ws * 8 + j;
            u64 c0 = 0ull, c1 = 0ull;
#pragma unroll
            for (int kp = 0; kp < 8; kp++) {
                ulonglong2 t = t2s[wp * 9 + kp];
                c0 = ffma2(z0[2*kp], t.x, c0); c0 = ffma2(z0[2*kp+1], t.y, c0);
                c1 = ffma2(z1[2*kp], t.x, c1); c1 = ffma2(z1[2*kp+1], t.y, c1);
            }
            {
                ulonglong2 t = t2s[wp * 9 + 8];
                c0 = ffma2(z0[16], t.x, c0);
                c1 = ffma2(z1[16], t.x, c1);
            }
            float2 f0 = upk(c0), f1 = upk(c1);
            y0[wp * CC + o] = bo + f0.x - f0.y;
            y1[wp * CC + o] = bo + f1.x - f1.y;
            if (wp > 0 && wp < 128) {
                y0[(256 - wp) * CC + o] = bo + f0.x + f0.y;
                y1[(256 - wp) * CC + o] = bo + f1.x + f1.y;
            }
        }
    }
}

// ---------------------------------------------------------------------------
extern "C" void kernel_launch(void* const* d_in, const int* in_sizes, int n_in,
                              void* d_out, int out_size) {
    const float* x    = (const float*)d_in[0];
    const float* w1r  = (const float*)d_in[1];
    const float* w1i  = (const float*)d_in[2];
    const float* w2r  = (const float*)d_in[3];
    const float* w2i  = (const float*)d_in[4];
    const float* bias = (const float*)d_in[5];
    float* y = (float*)d_out;

    cudaFuncSetAttribute(kA, cudaFuncAttributeMaxDynamicSharedMemorySize, 83968);
    cudaFuncSetAttribute(kB, cudaFuncAttributeMaxDynamicSharedMemorySize, 65024);
    cudaFuncSetAttribute(kC, cudaFuncAttributeMaxDynamicSharedMemorySize, 81920);
    cudaFuncSetAttribute(kD, cudaFuncAttributeMaxDynamicSharedMemorySize, 53520);

    k_init<<<26, 256>>>();
    k_wt2<<<(NKH * EM1_ * CC * CC + 255) / 256, 256>>>(w1r, w1i, w2r, w2i);
    kA <<<BB * HH / 2, 256, 83968>>>(x);
    kB <<<BB * EM1_, 256, 65024>>>();
    kC <<<EM1_ * 8, 256, 81920>>>();
    kSD<<<BB * EM1_, 544>>>();
    kD <<<BB * HH / 8, 544, 53520>>>(bias, y);
}